// round 11
// baseline (speedup 1.0000x reference)
#include <cuda_runtime.h>
#include <cuda_bf16.h>

// k-winners-take-all: x (rows=200704, C=256) fp32. Keep x >= 26th largest per row.
// Warp-per-row, NO per-lane sort. Count via FSET masks (set.ge.u32.f32):
// 8 masks + 4 IADD3 = -cnt per lane, REDUX.SUM across warp. Bisection on
// positive-float bit patterns, count-exact exits (tot==26 min-of-winners,
// tot==25 max-of-losers) using the live masks. Cold path (T<0, ~never): radix.

constexpr int CHANNELS = 256;
constexpr unsigned KSEL = 26;   // max(1, round(0.1 * 256))

__device__ __forceinline__ unsigned f2k(float f) {          // order-preserving key
    unsigned u = __float_as_uint(f);
    unsigned m = (unsigned)((int)u >> 31);
    return u ^ (m | 0x80000000u);
}

// FSET: all-ones mask if a >= c else 0 (single alu instruction)
__device__ __forceinline__ unsigned geMask(float a, float c) {
    unsigned m;
    asm("set.ge.u32.f32 %0, %1, %2;" : "=r"(m) : "f"(a), "f"(c));
    return m;
}

// d = (a & m) | (b & ~m)  -- single LOP3
__device__ __forceinline__ unsigned selBits(unsigned a, unsigned b, unsigned m) {
    return (a & m) | (b & ~m);
}

__global__ void __launch_bounds__(256)
kwta_kernel(const float* __restrict__ x, float* __restrict__ y, int rows) {
    int gw = (blockIdx.x * blockDim.x + threadIdx.x) >> 5;
    if (gw >= rows) return;
    int lane = threadIdx.x & 31;

    const float4* xp = reinterpret_cast<const float4*>(x) + (size_t)gw * (CHANNELS / 4);
    float4 a = __ldcs(xp + lane);
    float4 b = __ldcs(xp + 32 + lane);

    float f0 = a.x, f1 = a.y, f2 = a.z, f3 = a.w;
    float f4 = b.x, f5 = b.y, f6 = b.z, f7 = b.w;

    // lane max (7 FMNMX) -> warp bounds
    float lmax = fmaxf(fmaxf(fmaxf(f0, f1), fmaxf(f2, f3)),
                       fmaxf(fmaxf(f4, f5), fmaxf(f6, f7)));
    unsigned kmax = f2k(lmax);
    unsigned keyL = __reduce_min_sync(0xFFFFFFFFu, kmax);   // min lane-max: cnt_ge >= 32
    unsigned keyM = __reduce_max_sync(0xFFFFFFFFu, kmax);   // warp max

    // per-lane negative count of {f_j >= c}: 8 FSET + 4 IADD3
    auto negCnt = [&](float c) -> int {
        unsigned m0 = geMask(f0, c), m1 = geMask(f1, c);
        unsigned m2 = geMask(f2, c), m3 = geMask(f3, c);
        unsigned m4 = geMask(f4, c), m5 = geMask(f5, c);
        unsigned m6 = geMask(f6, c), m7 = geMask(f7, c);
        return (int)(m0 + m1 + m2 + m3 + m4 + m5 + m6 + m7);   // = -cnt
    };

    float thrf;
    bool cold = false;
    unsigned lo = 0u;

    if (keyL >= 0x80000000u) {
        lo = keyL ^ 0x80000000u;   // positive pattern; cnt_ge(lo) >= 32 >= KSEL
    } else {
        int nt = __reduce_add_sync(0xFFFFFFFFu, negCnt(0.0f));
        if (-nt < (int)KSEL) cold = true;        // threshold negative
    }

    if (!cold) {
        // ---- HOT: T >= 0, bisection over positive patterns in [lo, hi) ----
        unsigned hi = (keyM ^ 0x80000000u) + 1u;  // cnt_ge(hi) == 0 exactly
        unsigned thrkey;

        if (hi - lo <= 1u) {
            thrkey = lo;
        } else {
            unsigned mid = lo + ((hi - lo) >> 5) * 19u;   // prior ~0.59 of bracket
            if (mid == lo) mid = lo + 1u;

            #pragma unroll 1
            for (;;) {
                float c = __uint_as_float(mid);
                unsigned m0 = geMask(f0, c), m1 = geMask(f1, c);
                unsigned m2 = geMask(f2, c), m3 = geMask(f3, c);
                unsigned m4 = geMask(f4, c), m5 = geMask(f5, c);
                unsigned m6 = geMask(f6, c), m7 = geMask(f7, c);
                int part = (int)(m0 + m1 + m2 + m3 + m4 + m5 + m6 + m7);
                int ntot = __reduce_add_sync(0xFFFFFFFFu, part);   // = -tot

                if (ntot == -(int)KSEL) {
                    // exactly 26 winners (>= c): T = min winner. Winners >= c >= 0,
                    // positive patterns order like floats; losers -> +inf pattern.
                    unsigned w = 0x7F800000u;
                    w = umin(w, selBits(__float_as_uint(f0), 0x7F800000u, m0));
                    w = umin(w, selBits(__float_as_uint(f1), 0x7F800000u, m1));
                    w = umin(w, selBits(__float_as_uint(f2), 0x7F800000u, m2));
                    w = umin(w, selBits(__float_as_uint(f3), 0x7F800000u, m3));
                    w = umin(w, selBits(__float_as_uint(f4), 0x7F800000u, m4));
                    w = umin(w, selBits(__float_as_uint(f5), 0x7F800000u, m5));
                    w = umin(w, selBits(__float_as_uint(f6), 0x7F800000u, m6));
                    w = umin(w, selBits(__float_as_uint(f7), 0x7F800000u, m7));
                    thrkey = __reduce_min_sync(0xFFFFFFFFu, w);
                    break;
                }
                if (ntot == -(int)(KSEL - 1u)) {
                    // exactly 25 winners: T = max loser (known >= 0).
                    // Clamp negatives to +0 so loser bit patterns order like floats.
                    unsigned w = 0u;
                    w = umax(w, __float_as_uint(fmaxf(f0, 0.0f)) & ~m0);
                    w = umax(w, __float_as_uint(fmaxf(f1, 0.0f)) & ~m1);
                    w = umax(w, __float_as_uint(fmaxf(f2, 0.0f)) & ~m2);
                    w = umax(w, __float_as_uint(fmaxf(f3, 0.0f)) & ~m3);
                    w = umax(w, __float_as_uint(fmaxf(f4, 0.0f)) & ~m4);
                    w = umax(w, __float_as_uint(fmaxf(f5, 0.0f)) & ~m5);
                    w = umax(w, __float_as_uint(fmaxf(f6, 0.0f)) & ~m6);
                    w = umax(w, __float_as_uint(fmaxf(f7, 0.0f)) & ~m7);
                    thrkey = __reduce_max_sync(0xFFFFFFFFu, w);
                    break;
                }
                if (ntot < -(int)KSEL) lo = mid; else hi = mid;  // tot>=27 / tot<=24
                if (hi - lo <= 1u) { thrkey = lo; break; }       // lo == bits(T)
                mid = lo + ((hi - lo) >> 1);
            }
        }
        thrf = __uint_as_float(thrkey);
    } else {
        // ---- COLD: T < 0. Plain exact 32-step key-domain MSB radix. ----
        unsigned s0 = f2k(f0), s1 = f2k(f1), s2 = f2k(f2), s3 = f2k(f3);
        unsigned s4 = f2k(f4), s5 = f2k(f5), s6 = f2k(f6), s7 = f2k(f7);
        unsigned prefix = 0u;
        #pragma unroll 1
        for (int bit = 31; bit >= 0; --bit) {
            unsigned cand = prefix | (1u << bit);
            unsigned cnt = (unsigned)(s0 >= cand) + (unsigned)(s1 >= cand)
                         + (unsigned)(s2 >= cand) + (unsigned)(s3 >= cand)
                         + (unsigned)(s4 >= cand) + (unsigned)(s5 >= cand)
                         + (unsigned)(s6 >= cand) + (unsigned)(s7 >= cand);
            unsigned tot = __reduce_add_sync(0xFFFFFFFFu, cnt);
            if (tot >= KSEL) prefix = cand;
        }
        // prefix == key of the KSEL-th largest element (exact)
        unsigned tu = (prefix & 0x80000000u) ? (prefix ^ 0x80000000u) : ~prefix;
        thrf = __uint_as_float(tu);
    }

    float4 oa, ob;
    oa.x = (a.x >= thrf) ? a.x : 0.0f;
    oa.y = (a.y >= thrf) ? a.y : 0.0f;
    oa.z = (a.z >= thrf) ? a.z : 0.0f;
    oa.w = (a.w >= thrf) ? a.w : 0.0f;
    ob.x = (b.x >= thrf) ? b.x : 0.0f;
    ob.y = (b.y >= thrf) ? b.y : 0.0f;
    ob.z = (b.z >= thrf) ? b.z : 0.0f;
    ob.w = (b.w >= thrf) ? b.w : 0.0f;

    float4* yp = reinterpret_cast<float4*>(y) + (size_t)gw * (CHANNELS / 4);
    __stcs(yp + lane, oa);
    __stcs(yp + 32 + lane, ob);
}

extern "C" void kernel_launch(void* const* d_in, const int* in_sizes, int n_in,
                              void* d_out, int out_size) {
    const float* x = (const float*)d_in[0];
    float* y = (float*)d_out;
    int rows = in_sizes[0] / CHANNELS;            // 200704
    int total_threads = rows * 32;                // one warp per row
    int block = 256;
    int grid = (total_threads + block - 1) / block;
    kwta_kernel<<<grid, block>>>(x, y, rows);
}

// round 14
// speedup vs baseline: 1.0861x; 1.0861x over previous
#include <cuda_runtime.h>
#include <cuda_bf16.h>

// k-winners-take-all: x (rows=200704, C=256) fp32. Keep x >= 26th largest per row.
// Warp-per-row. Hot path: lean bisection on positive-float bit patterns (prior
// first probe at 0.59 of bracket) with WIDE count-exact exits:
//   tot==27 -> 2nd-smallest winner, tot==26 -> min winner,
//   tot==25 -> max loser,           tot==24 -> 2nd-largest loser.
// Cold path (T<0, ~never on this data, exactness only): 32-step key radix.

constexpr int CHANNELS = 256;
constexpr unsigned KSEL = 26;       // max(1, round(0.1 * 256))
constexpr unsigned FULL = 0xFFFFFFFFu;

__device__ __forceinline__ void ceF(float &a, float &b) {   // a<-max, b<-min
    float hi = fmaxf(a, b), lo = fminf(a, b);
    a = hi; b = lo;
}

__device__ __forceinline__ unsigned f2k(float f) {          // order-preserving key
    unsigned u = __float_as_uint(f);
    unsigned m = (unsigned)((int)u >> 31);
    return u ^ (m | 0x80000000u);
}

__global__ void __launch_bounds__(256)
kwta_kernel(const float* __restrict__ x, float* __restrict__ y, int rows) {
    int gw = (blockIdx.x * blockDim.x + threadIdx.x) >> 5;
    if (gw >= rows) return;
    int lane = threadIdx.x & 31;

    const float4* xp = reinterpret_cast<const float4*>(x) + (size_t)gw * (CHANNELS / 4);
    float4 a = __ldcs(xp + lane);
    float4 b = __ldcs(xp + 32 + lane);

    float f0 = a.x, f1 = a.y, f2 = a.z, f3 = a.w;
    float f4 = b.x, f5 = b.y, f6 = b.z, f7 = b.w;

    // Batcher odd-even mergesort for 8, descending (19 CE)
    ceF(f0,f1); ceF(f2,f3); ceF(f4,f5); ceF(f6,f7);
    ceF(f0,f2); ceF(f1,f3); ceF(f4,f6); ceF(f5,f7);
    ceF(f1,f2); ceF(f5,f6);
    ceF(f0,f4); ceF(f1,f5); ceF(f2,f6); ceF(f3,f7);
    ceF(f2,f4); ceF(f3,f5);
    ceF(f1,f2); ceF(f3,f4); ceF(f5,f6);
    // f0 >= f1 >= ... >= f7

    // per-lane count of {f_j >= c}: branchless binary search on sorted regs
    auto cnt8 = [&](float c) -> unsigned {
        bool c1 = (f3 >= c);
        float t1 = c1 ? f5 : f1;
        bool c2 = (t1 >= c);
        float tA = c2 ? f2 : f0;
        float tB = c2 ? f6 : f4;
        float t2 = c1 ? tB : tA;
        bool c3 = (t2 >= c);
        bool c0 = (f7 >= c);
        return 4u*(unsigned)c1 + 2u*(unsigned)c2 + (unsigned)c3 + (unsigned)c0;
    };

    // Exact threshold when a probe lands at tot in {24,25,26,27}.
    // Hot path only: probe cf > float(lo) >= 0 and T >= 0, so winner patterns
    // order like floats; losers clamped to +0 also order like floats.
    auto resolveExit = [&](float cf, unsigned tot) -> unsigned {
        const float INF = __int_as_float(0x7F800000);
        if (tot >= KSEL) {
            // sorted desc: winners are a prefix of f0..f7.
            // lane min winner t = last f_j >= cf; 2nd-min u = previous one.
            float t = INF, u = INF;
            { bool w = (f0 >= cf); u = w ? t : u; t = w ? f0 : t; }
            { bool w = (f1 >= cf); u = w ? t : u; t = w ? f1 : t; }
            { bool w = (f2 >= cf); u = w ? t : u; t = w ? f2 : t; }
            { bool w = (f3 >= cf); u = w ? t : u; t = w ? f3 : t; }
            { bool w = (f4 >= cf); u = w ? t : u; t = w ? f4 : t; }
            { bool w = (f5 >= cf); u = w ? t : u; t = w ? f5 : t; }
            { bool w = (f6 >= cf); u = w ? t : u; t = w ? f6 : t; }
            { bool w = (f7 >= cf); u = w ? t : u; t = w ? f7 : t; }
            unsigned bt = __float_as_uint(t), bu = __float_as_uint(u);
            unsigned m1 = __reduce_min_sync(FULL, bt);      // global min winner
            if (tot == KSEL) return m1;
            // tot==27: need 2nd-smallest winner (ties: if the min pattern occurs
            // in >1 lane, the 2nd-smallest equals the min).
            bool eq = (bt == m1);
            unsigned v  = eq ? bu : bt;
            unsigned m2 = __reduce_min_sync(FULL, v);
            unsigned nt = __popc(__ballot_sync(FULL, eq));
            return (nt > 1u) ? m1 : m2;
        } else {
            // losers are a suffix of f0..f7 (sorted desc).
            // lane max loser t = first f_j < cf; 2nd-max u = next one.
            float t = -INF, u = -INF;
            { bool w = (f7 < cf); u = w ? t : u; t = w ? f7 : t; }
            { bool w = (f6 < cf); u = w ? t : u; t = w ? f6 : t; }
            { bool w = (f5 < cf); u = w ? t : u; t = w ? f5 : t; }
            { bool w = (f4 < cf); u = w ? t : u; t = w ? f4 : t; }
            { bool w = (f3 < cf); u = w ? t : u; t = w ? f3 : t; }
            { bool w = (f2 < cf); u = w ? t : u; t = w ? f2 : t; }
            { bool w = (f1 < cf); u = w ? t : u; t = w ? f1 : t; }
            { bool w = (f0 < cf); u = w ? t : u; t = w ? f0 : t; }
            // T >= 0 => top-2 losers that matter are >= 0; clamp keeps order.
            unsigned bt = __float_as_uint(fmaxf(t, 0.0f));
            unsigned bu = __float_as_uint(fmaxf(u, 0.0f));
            unsigned m1 = __reduce_max_sync(FULL, bt);      // global max loser
            if (tot == KSEL - 1u) return m1;
            // tot==24: 2nd-largest loser.
            bool eq = (bt == m1);
            unsigned v  = eq ? bu : bt;
            unsigned m2 = __reduce_max_sync(FULL, v);
            unsigned nt = __popc(__ballot_sync(FULL, eq));
            return (nt > 1u) ? m1 : m2;
        }
    };

    unsigned k0   = f2k(f0);                          // lane-max key
    unsigned keyL = __reduce_min_sync(FULL, k0);      // min lane-max: cnt_ge >= 32
    unsigned keyM = __reduce_max_sync(FULL, k0);      // warp max

    float thrf;
    bool cold = false;
    unsigned lo = 0u;

    if (keyL >= 0x80000000u) {
        lo = keyL ^ 0x80000000u;      // positive pattern; cnt_ge(lo) >= 32 >= KSEL
    } else {
        unsigned cp = __reduce_add_sync(FULL, cnt8(0.0f));
        if (cp < KSEL) cold = true;   // threshold negative
    }

    if (!cold) {
        // ---- HOT: T >= 0, bisection over positive patterns in [lo, hi) ----
        unsigned hi = (keyM ^ 0x80000000u) + 1u;      // cnt_ge(hi) == 0 exactly
        unsigned thrkey;

        if (hi - lo <= 1u) {
            thrkey = lo;
        } else {
            // prior-placed first probe (~0.59 of bracket); pure bisection after
            unsigned mid = lo + ((hi - lo) >> 5) * 19u;
            if (mid == lo) mid = lo + 1u;

            #pragma unroll 1
            for (;;) {
                float c = __uint_as_float(mid);
                unsigned tot = __reduce_add_sync(FULL, cnt8(c));

                if (tot - (KSEL - 2u) <= 3u) {        // tot in {24,25,26,27}
                    thrkey = resolveExit(c, tot);
                    break;
                }
                if (tot > KSEL) lo = mid; else hi = mid;   // tot>=28 / tot<=23
                if (hi - lo <= 1u) { thrkey = lo; break; } // lo == bits(T) exactly
                mid = lo + ((hi - lo) >> 1);               // bisect: <= 33 iters
            }
        }
        thrf = __uint_as_float(thrkey);
    } else {
        // ---- COLD: T < 0. Exact 32-step key-domain MSB radix. ----
        unsigned s0 = f2k(f0), s1 = f2k(f1), s2 = f2k(f2), s3 = f2k(f3);
        unsigned s4 = f2k(f4), s5 = f2k(f5), s6 = f2k(f6), s7 = f2k(f7);
        unsigned prefix = 0u;
        #pragma unroll 1
        for (int bit = 31; bit >= 0; --bit) {
            unsigned cand = prefix | (1u << bit);
            unsigned cnt = (unsigned)(s0 >= cand) + (unsigned)(s1 >= cand)
                         + (unsigned)(s2 >= cand) + (unsigned)(s3 >= cand)
                         + (unsigned)(s4 >= cand) + (unsigned)(s5 >= cand)
                         + (unsigned)(s6 >= cand) + (unsigned)(s7 >= cand);
            unsigned tot = __reduce_add_sync(FULL, cnt);
            if (tot >= KSEL) prefix = cand;
        }
        unsigned tu = (prefix & 0x80000000u) ? (prefix ^ 0x80000000u) : ~prefix;
        thrf = __uint_as_float(tu);
    }

    float4 oa, ob;
    oa.x = (a.x >= thrf) ? a.x : 0.0f;
    oa.y = (a.y >= thrf) ? a.y : 0.0f;
    oa.z = (a.z >= thrf) ? a.z : 0.0f;
    oa.w = (a.w >= thrf) ? a.w : 0.0f;
    ob.x = (b.x >= thrf) ? b.x : 0.0f;
    ob.y = (b.y >= thrf) ? b.y : 0.0f;
    ob.z = (b.z >= thrf) ? b.z : 0.0f;
    ob.w = (b.w >= thrf) ? b.w : 0.0f;

    float4* yp = reinterpret_cast<float4*>(y) + (size_t)gw * (CHANNELS / 4);
    __stcs(yp + lane, oa);
    __stcs(yp + 32 + lane, ob);
}

extern "C" void kernel_launch(void* const* d_in, const int* in_sizes, int n_in,
                              void* d_out, int out_size) {
    const float* x = (const float*)d_in[0];
    float* y = (float*)d_out;
    int rows = in_sizes[0] / CHANNELS;            // 200704
    int total_threads = rows * 32;                // one warp per row
    int block = 256;
    int grid = (total_threads + block - 1) / block;
    kwta_kernel<<<grid, block>>>(x, y, rows);
}